// round 1
// baseline (speedup 1.0000x reference)
#include <cuda_runtime.h>

#define BB 256
#define TT 50
#define MM 20
#define EE 128
#define G3 384

// scratch (no cudaMalloc allowed)
__device__ __align__(16) float g_ub[BB*TT*EE];   // basket means   (B,T,E)
__device__ __align__(16) float g_xg[BB*TT*G3];   // input gates    (B,T,3E)

typedef unsigned long long u64;

__device__ __forceinline__ void fma2(u64 &acc, u64 a, u64 b){
    asm("fma.rn.f32x2 %0, %1, %2, %0;" : "+l"(acc) : "l"(a), "l"(b));
}
__device__ __forceinline__ float hsum2(u64 v){
    float lo, hi;
    asm("mov.b64 {%0,%1}, %2;" : "=f"(lo), "=f"(hi) : "l"(v));
    return lo + hi;
}

// ---------------------------------------------------------------------------
// K1: ub[b,t,:] = (1/basket) * sum_m emb[item_ids[b,t,m]]   (emb[0] == 0)
// ---------------------------------------------------------------------------
__global__ void k_gather(const int* __restrict__ ids, const int* __restrict__ bsz,
                         const float* __restrict__ emb){
    int bt = blockIdx.x;
    __shared__ int sid[MM];
    int tid = threadIdx.x;
    if (tid < MM) sid[tid] = ids[bt*MM + tid];
    __syncthreads();
    float a0=0.f, a1=0.f, a2=0.f, a3=0.f;
    #pragma unroll
    for (int m = 0; m < MM; m += 4){
        a0 += emb[sid[m+0]*EE + tid];
        a1 += emb[sid[m+1]*EE + tid];
        a2 += emb[sid[m+2]*EE + tid];
        a3 += emb[sid[m+3]*EE + tid];
    }
    float inv = 1.0f / (float)bsz[bt];
    g_ub[bt*EE + tid] = (a0+a1+a2+a3) * inv;
}

// ---------------------------------------------------------------------------
// K2: xg[row, j] = dot(W_ih[j,:], ub[row,:]) + b_ih[j]
// 128 CTAs x 384 threads; thread j owns W_ih row j as 64 f32x2 registers.
// 2 rows per iteration, 50 iterations, register-prefetch double buffering.
// ---------------------------------------------------------------------------
__global__ void __launch_bounds__(384,1) k_xg(const float* __restrict__ W_ih,
                                              const float* __restrict__ b_ih){
    const int j = threadIdx.x;
    u64 w[64];
    const u64* wrow = (const u64*)(W_ih + j*EE);
    #pragma unroll
    for (int k = 0; k < 64; ++k) w[k] = wrow[k];
    const float bias = b_ih[j];

    __shared__ __align__(16) float su[2][2][EE];   // [buf][row][e]

    const int base = blockIdx.x * 100;             // 128 CTAs * 100 rows = 12800
    const int rr = j >> 5, lane = j & 31;

    if (j < 64)
        ((float4*)su[0][rr])[lane] = ((const float4*)(g_ub + (base+rr)*EE))[lane];
    __syncthreads();

    for (int it = 0; it < 50; ++it){
        const int cur = it & 1, nxt = cur ^ 1;
        float4 pf;
        if (j < 64 && it+1 < 50)
            pf = ((const float4*)(g_ub + (base + (it+1)*2 + rr)*EE))[lane];

        u64 a0a=0ull, a0b=0ull, a1a=0ull, a1b=0ull;
        const ulonglong2* h0p = (const ulonglong2*)su[cur][0];
        const ulonglong2* h1p = (const ulonglong2*)su[cur][1];
        #pragma unroll
        for (int k = 0; k < 32; ++k){
            ulonglong2 v0 = h0p[k], v1 = h1p[k];
            fma2(a0a, w[2*k  ], v0.x);
            fma2(a0b, w[2*k+1], v0.y);
            fma2(a1a, w[2*k  ], v1.x);
            fma2(a1b, w[2*k+1], v1.y);
        }
        const int r0 = base + it*2;
        g_xg[ r0   *G3 + j] = hsum2(a0a) + hsum2(a0b) + bias;
        g_xg[(r0+1)*G3 + j] = hsum2(a1a) + hsum2(a1b) + bias;

        if (j < 64 && it+1 < 50)
            ((float4*)su[nxt][rr])[lane] = pf;
        __syncthreads();
    }
}

// ---------------------------------------------------------------------------
// K3: masked GRU scan. 128 CTAs x 384 threads; CTA handles batch rows 2b, 2b+1.
// W_hh row j in registers for all 50 steps; h in shared; 2 syncs per step.
// ---------------------------------------------------------------------------
__global__ void __launch_bounds__(384,1) k_scan(const float* __restrict__ W_hh,
                                                const float* __restrict__ b_hh,
                                                const float* __restrict__ h0,
                                                const int*   __restrict__ lengths,
                                                float* __restrict__ out){
    const int j  = threadIdx.x;
    const int b0 = blockIdx.x * 2, b1 = b0 + 1;

    u64 w[64];
    const u64* wrow = (const u64*)(W_hh + j*EE);
    #pragma unroll
    for (int k = 0; k < 64; ++k) w[k] = wrow[k];
    const float bias = b_hh[j];
    const int len0 = lengths[b0], len1 = lengths[b1];

    __shared__ __align__(16) float sh[2][EE];     // hidden state
    __shared__ float srz[2][256];                 // r|z pre-activations
    __shared__ float shn[2][EE];                  // hn (recurrent n part)
    __shared__ float sxn[2][EE];                  // xn (input n part)

    if (j < 256){
        int row = j >> 7, e = j & 127;
        sh[row][e] = h0[(row ? b1 : b0)*EE + e];
    }
    __syncthreads();

    for (int t = 0; t < TT; ++t){
        // prefetch xg (hidden under FMA block)
        const float xg0 = g_xg[(b0*TT + t)*G3 + j];
        const float xg1 = g_xg[(b1*TT + t)*G3 + j];

        u64 a0a=0ull, a0b=0ull, a1a=0ull, a1b=0ull;
        const ulonglong2* h0p = (const ulonglong2*)sh[0];
        const ulonglong2* h1p = (const ulonglong2*)sh[1];
        #pragma unroll
        for (int k = 0; k < 32; ++k){
            ulonglong2 v0 = h0p[k], v1 = h1p[k];
            fma2(a0a, w[2*k  ], v0.x);
            fma2(a0b, w[2*k+1], v0.y);
            fma2(a1a, w[2*k  ], v1.x);
            fma2(a1b, w[2*k+1], v1.y);
        }
        const float hg0 = hsum2(a0a) + hsum2(a0b) + bias;
        const float hg1 = hsum2(a1a) + hsum2(a1b) + bias;

        if (j < 256){
            srz[0][j] = hg0 + xg0;       // biases: b_ih already in xg, b_hh in hg
            srz[1][j] = hg1 + xg1;
        } else {
            const int e = j - 256;
            shn[0][e] = hg0;  sxn[0][e] = xg0;
            shn[1][e] = hg1;  sxn[1][e] = xg1;
        }
        __syncthreads();

        if (j < 256){
            const int row = j >> 7, e = j & 127;
            const float r  = 1.f / (1.f + __expf(-srz[row][e]));
            const float z  = 1.f / (1.f + __expf(-srz[row][e+128]));
            const float n  = tanhf(sxn[row][e] + r * shn[row][e]);
            const float hp = sh[row][e];
            const float hv = (1.f - z) * n + z * hp;
            const int  len = row ? len1 : len0;
            const bool mk  = t < len;
            sh[row][e] = mk ? hv : hp;
            out[((row ? b1 : b0)*TT + t)*EE + e] = mk ? hv : 0.f;
        }
        __syncthreads();
    }

    if (j < 256){
        const int row = j >> 7, e = j & 127;
        out[BB*TT*EE + (row ? b1 : b0)*EE + e] = sh[row][e];
    }
}

// ---------------------------------------------------------------------------
extern "C" void kernel_launch(void* const* d_in, const int* in_sizes, int n_in,
                              void* d_out, int out_size){
    const int*   item_ids = (const int*)  d_in[0];
    const int*   bsz      = (const int*)  d_in[1];
    const int*   lengths  = (const int*)  d_in[2];
    const float* emb      = (const float*)d_in[3];
    const float* W_ih     = (const float*)d_in[4];
    const float* W_hh     = (const float*)d_in[5];
    const float* b_ih     = (const float*)d_in[6];
    const float* b_hh     = (const float*)d_in[7];
    const float* h0       = (const float*)d_in[8];
    float* out = (float*)d_out;

    k_gather<<<BB*TT, EE>>>(item_ids, bsz, emb);
    k_xg   <<<128, 384>>>(W_ih, b_ih);
    k_scan <<<128, 384>>>(W_hh, b_hh, h0, lengths, out);
}

// round 2
// speedup vs baseline: 1.4715x; 1.4715x over previous
#include <cuda_runtime.h>

#define BB 256
#define TT 50
#define MM 20
#define EE 128
#define G3 384

// scratch (no cudaMalloc allowed); .bss -> zero at module load.
// Slots for t >= len are NEVER written, so they stay 0 forever (deterministic).
__device__ __align__(16) float g_ub[BB*TT*EE];   // basket means   (B,T,E)
__device__ __align__(16) float g_xg[BB*TT*G3];   // input gates    (B,T,3E)

typedef unsigned long long u64;

__device__ __forceinline__ void fma2(u64 &acc, u64 a, u64 b){
    asm("fma.rn.f32x2 %0, %1, %2, %0;" : "+l"(acc) : "l"(a), "l"(b));
}
__device__ __forceinline__ float hsum2(u64 v){
    float lo, hi;
    asm("mov.b64 {%0,%1}, %2;" : "=f"(lo), "=f"(hi) : "l"(v));
    return lo + hi;
}
__device__ __forceinline__ float sigf(float x){
    return __fdividef(1.f, 1.f + __expf(-x));
}
__device__ __forceinline__ float tanhfast(float x){
    return __fdividef(2.f, 1.f + __expf(-2.f*x)) - 1.f;
}

// ---------------------------------------------------------------------------
// K1: ub[b,t,:] = (1/basket) * sum_m emb[item_ids[b,t,m]]   (emb[0] == 0)
// No shared staging, no barriers; skip t >= len[b].
// ---------------------------------------------------------------------------
__global__ void k_gather(const int* __restrict__ ids, const int* __restrict__ bsz,
                         const int* __restrict__ lens, const float* __restrict__ emb){
    const int bt = blockIdx.x;
    const int b  = bt / TT;
    const int t  = bt - b*TT;
    if (t >= __ldg(lens + b)) return;            // ub never read for masked t

    const int tid = threadIdx.x;
    const int4* ip = (const int4*)(ids + bt*MM); // 20 ids = 5 int4 (16B aligned)
    int4 i0 = __ldg(ip+0), i1 = __ldg(ip+1), i2 = __ldg(ip+2),
         i3 = __ldg(ip+3), i4 = __ldg(ip+4);

    float a0 = emb[i0.x*EE+tid] + emb[i0.y*EE+tid] + emb[i0.z*EE+tid] + emb[i0.w*EE+tid];
    float a1 = emb[i1.x*EE+tid] + emb[i1.y*EE+tid] + emb[i1.z*EE+tid] + emb[i1.w*EE+tid];
    float a2 = emb[i2.x*EE+tid] + emb[i2.y*EE+tid] + emb[i2.z*EE+tid] + emb[i2.w*EE+tid];
    float a3 = emb[i3.x*EE+tid] + emb[i3.y*EE+tid] + emb[i3.z*EE+tid] + emb[i3.w*EE+tid];
    float a4 = emb[i4.x*EE+tid] + emb[i4.y*EE+tid] + emb[i4.z*EE+tid] + emb[i4.w*EE+tid];

    const float inv = 1.0f / (float)__ldg(bsz + bt);
    g_ub[bt*EE + tid] = ((a0+a1) + (a2+a3) + a4) * inv;
}

// ---------------------------------------------------------------------------
// K2: xg[row, j] = dot(W_ih[j,:], ub[row,:]) + b_ih[j]
// CTA i handles the batch PAIR (i, 255-i) -> balanced work ~ (len_i+len_{255-i})/2.
// Thread j owns W_ih row j as 64 f32x2 registers. Skips t >= len.
// ---------------------------------------------------------------------------
__global__ void __launch_bounds__(384,1) k_xg(const float* __restrict__ W_ih,
                                              const float* __restrict__ b_ih,
                                              const int*   __restrict__ lens){
    const int j = threadIdx.x;
    u64 w[64];
    const u64* wrow = (const u64*)(W_ih + j*EE);
    #pragma unroll
    for (int k = 0; k < 64; ++k) w[k] = wrow[k];
    const float bias = b_ih[j];

    const int b0 = blockIdx.x;
    const int b1 = (BB-1) - blockIdx.x;
    const int len0 = lens[b0], len1 = lens[b1];
    const int maxlen = max(len0, len1);

    __shared__ __align__(16) float su[2][2][EE];   // [buf][rowpair][e]

    const int rr = j >> 5, lane = j & 31;

    if (j < 64){                                   // preload t = 0 (len >= 1 always)
        const int bb = rr ? b1 : b0;
        ((float4*)su[0][rr])[lane] = ((const float4*)(g_ub + (bb*TT)*EE))[lane];
    }
    __syncthreads();

    for (int t = 0; t < maxlen; ++t){
        const int cur = t & 1, nxt = cur ^ 1;
        float4 pf; bool havepf = false;
        if (j < 64){
            const int bb = rr ? b1 : b0;
            const int ln = rr ? len1 : len0;
            if (t+1 < ln){
                pf = ((const float4*)(g_ub + (bb*TT + t+1)*EE))[lane];
                havepf = true;
            }
        }

        const bool a0 = (t < len0), a1 = (t < len1);
        if (a0 && a1){
            u64 c0a=0ull, c0b=0ull, c1a=0ull, c1b=0ull;
            const ulonglong2* h0p = (const ulonglong2*)su[cur][0];
            const ulonglong2* h1p = (const ulonglong2*)su[cur][1];
            #pragma unroll
            for (int k = 0; k < 32; ++k){
                ulonglong2 v0 = h0p[k], v1 = h1p[k];
                fma2(c0a, w[2*k  ], v0.x);
                fma2(c0b, w[2*k+1], v0.y);
                fma2(c1a, w[2*k  ], v1.x);
                fma2(c1b, w[2*k+1], v1.y);
            }
            g_xg[(b0*TT + t)*G3 + j] = hsum2(c0a) + hsum2(c0b) + bias;
            g_xg[(b1*TT + t)*G3 + j] = hsum2(c1a) + hsum2(c1b) + bias;
        } else {
            const ulonglong2* hp = (const ulonglong2*)su[cur][a0 ? 0 : 1];
            const int bb = a0 ? b0 : b1;
            u64 ca=0ull, cb=0ull;
            #pragma unroll
            for (int k = 0; k < 32; ++k){
                ulonglong2 v = hp[k];
                fma2(ca, w[2*k  ], v.x);
                fma2(cb, w[2*k+1], v.y);
            }
            g_xg[(bb*TT + t)*G3 + j] = hsum2(ca) + hsum2(cb) + bias;
        }

        if (havepf)
            ((float4*)su[nxt][rr])[lane] = pf;
        __syncthreads();
    }
}

// ---------------------------------------------------------------------------
// K3: masked GRU scan. CTA i handles batch pair (i, 255-i); loops to maxlen,
// zero-fills the masked tail of `out` afterwards. Fast sigmoid/tanh via MUFU.
// ---------------------------------------------------------------------------
__global__ void __launch_bounds__(384,1) k_scan(const float* __restrict__ W_hh,
                                                const float* __restrict__ b_hh,
                                                const float* __restrict__ h0,
                                                const int*   __restrict__ lens,
                                                float* __restrict__ out){
    const int j  = threadIdx.x;
    const int b0 = blockIdx.x;
    const int b1 = (BB-1) - blockIdx.x;

    u64 w[64];
    const u64* wrow = (const u64*)(W_hh + j*EE);
    #pragma unroll
    for (int k = 0; k < 64; ++k) w[k] = wrow[k];
    const float bias = b_hh[j];
    const int len0 = lens[b0], len1 = lens[b1];
    const int maxlen = max(len0, len1);

    __shared__ __align__(16) float sh[2][EE];     // hidden state
    __shared__ float srz[2][256];                 // r|z pre-activations
    __shared__ float shn[2][EE];                  // hn (recurrent n part)
    __shared__ float sxn[2][EE];                  // xn (input n part)

    if (j < 256){
        int row = j >> 7, e = j & 127;
        sh[row][e] = h0[(row ? b1 : b0)*EE + e];
    }
    __syncthreads();

    for (int t = 0; t < maxlen; ++t){
        const bool a0 = (t < len0), a1 = (t < len1);
        const float xg0 = a0 ? __ldg(&g_xg[(b0*TT + t)*G3 + j]) : 0.f;
        const float xg1 = a1 ? __ldg(&g_xg[(b1*TT + t)*G3 + j]) : 0.f;

        float hg0 = 0.f, hg1 = 0.f;
        if (a0 && a1){
            u64 c0a=0ull, c0b=0ull, c1a=0ull, c1b=0ull;
            const ulonglong2* h0p = (const ulonglong2*)sh[0];
            const ulonglong2* h1p = (const ulonglong2*)sh[1];
            #pragma unroll
            for (int k = 0; k < 32; ++k){
                ulonglong2 v0 = h0p[k], v1 = h1p[k];
                fma2(c0a, w[2*k  ], v0.x);
                fma2(c0b, w[2*k+1], v0.y);
                fma2(c1a, w[2*k  ], v1.x);
                fma2(c1b, w[2*k+1], v1.y);
            }
            hg0 = hsum2(c0a) + hsum2(c0b) + bias;
            hg1 = hsum2(c1a) + hsum2(c1b) + bias;
        } else {
            const ulonglong2* hp = (const ulonglong2*)sh[a0 ? 0 : 1];
            u64 ca=0ull, cb=0ull;
            #pragma unroll
            for (int k = 0; k < 32; ++k){
                ulonglong2 v = hp[k];
                fma2(ca, w[2*k  ], v.x);
                fma2(cb, w[2*k+1], v.y);
            }
            float hg = hsum2(ca) + hsum2(cb) + bias;
            if (a0) hg0 = hg; else hg1 = hg;
        }

        if (j < 256){
            srz[0][j] = hg0 + xg0;
            srz[1][j] = hg1 + xg1;
        } else {
            const int e = j - 256;
            shn[0][e] = hg0;  sxn[0][e] = xg0;
            shn[1][e] = hg1;  sxn[1][e] = xg1;
        }
        __syncthreads();

        if (j < 256){
            const int row = j >> 7, e = j & 127;
            const bool act = row ? a1 : a0;
            if (act){
                const float r  = sigf(srz[row][e]);
                const float z  = sigf(srz[row][e+128]);
                const float n  = tanhfast(sxn[row][e] + r * shn[row][e]);
                const float hp = sh[row][e];
                const float hv = (1.f - z) * n + z * hp;
                sh[row][e] = hv;
                out[((row ? b1 : b0)*TT + t)*EE + e] = hv;
            }
        }
        __syncthreads();
    }

    // zero-fill masked tail of dynamic_user (contiguous per batch row)
    {
        const float4 z4 = make_float4(0.f,0.f,0.f,0.f);
        float4* p0 = (float4*)(out + (b0*TT + len0)*EE);
        const int n0 = (TT - len0) * (EE/4);
        for (int k = j; k < n0; k += 384) p0[k] = z4;
        float4* p1 = (float4*)(out + (b1*TT + len1)*EE);
        const int n1 = (TT - len1) * (EE/4);
        for (int k = j; k < n1; k += 384) p1[k] = z4;
    }

    if (j < 256){
        const int row = j >> 7, e = j & 127;
        out[BB*TT*EE + (row ? b1 : b0)*EE + e] = sh[row][e];
    }
}

// ---------------------------------------------------------------------------
extern "C" void kernel_launch(void* const* d_in, const int* in_sizes, int n_in,
                              void* d_out, int out_size){
    const int*   item_ids = (const int*)  d_in[0];
    const int*   bsz      = (const int*)  d_in[1];
    const int*   lengths  = (const int*)  d_in[2];
    const float* emb      = (const float*)d_in[3];
    const float* W_ih     = (const float*)d_in[4];
    const float* W_hh     = (const float*)d_in[5];
    const float* b_ih     = (const float*)d_in[6];
    const float* b_hh     = (const float*)d_in[7];
    const float* h0       = (const float*)d_in[8];
    float* out = (float*)d_out;

    k_gather<<<BB*TT, EE>>>(item_ids, bsz, lengths, emb);
    k_xg   <<<128, 384>>>(W_ih, b_ih, lengths);
    k_scan <<<128, 384>>>(W_hh, b_hh, h0, lengths, out);
}